// round 6
// baseline (speedup 1.0000x reference)
#include <cuda_runtime.h>

static const int N_PAPER = 200000;
static const int N_MESH  = 30000;
static const int NNODES  = 230000;
static const int E_TR    = 2000000;
static const int E_P     = 500000;
static const int E_N     = 500000;
static const int NBLK_SCAN = (NNODES + 1023) / 1024;   // 225

typedef unsigned long long u64;

// ---- static device scratch ----
__device__ __align__(256) float g_x0[NNODES * 32];
__device__ __align__(256) float g_x1[NNODES * 32];
__device__ __align__(256) float g_Y[2 * NNODES * 32];   // [Y_rel0 ; Y_rel1]
__device__ __align__(256) int   g_ssel[E_TR];           // src + etype*NNODES
__device__ __align__(256) int   g_dst[E_TR];
__device__ __align__(256) int   g_eidx[E_TR];           // CSR buckets (ssel by dst)
__device__ __align__(256) int   g_cnt[NNODES];
__device__ __align__(256) int   g_rowptr[NNODES];
__device__ __align__(256) int   g_cursor[NNODES];
__device__ __align__(256) int   g_pre[NNODES];
__device__ __align__(256) int   g_bsum[NBLK_SCAN];
__device__ __align__(256) float g_W[2 * 32 * 32];

// ---- packed f32x2 helpers (FFMA2 is PTX-only) ----
__device__ __forceinline__ u64 pack2(float a, float b) {
    u64 r;
    asm("mov.b64 %0, {%1, %2};" : "=l"(r) : "r"(__float_as_uint(a)), "r"(__float_as_uint(b)));
    return r;
}
__device__ __forceinline__ u64 ffma2(u64 a, u64 b, u64 c) {
    u64 d;
    asm("fma.rn.f32x2 %0, %1, %2, %3;" : "=l"(d) : "l"(a), "l"(b), "l"(c));
    return d;
}
__device__ __forceinline__ float2 unpack2(u64 v) {
    unsigned lo, hi;
    asm("mov.b64 {%0, %1}, %2;" : "=r"(lo), "=r"(hi) : "l"(v));
    return make_float2(__uint_as_float(lo), __uint_as_float(hi));
}

// W[r] = sum_b comp[r,b] * basis[b]
__global__ void make_W_k(const float* __restrict__ comp, const float* __restrict__ basis,
                         float* __restrict__ W, int dio)
{
    int tot = 2 * dio;
    for (int i = blockIdx.x * blockDim.x + threadIdx.x; i < tot; i += gridDim.x * blockDim.x) {
        int r = i / dio, io = i % dio;
        float s = 0.f;
#pragma unroll
        for (int b = 0; b < 4; b++) s += comp[r * 4 + b] * basis[b * dio + io];
        W[i] = s;
    }
}

// ---- CSR build ----
__global__ void hist_k(const int* __restrict__ ei, const int* __restrict__ et,
                       int* __restrict__ ssel, int* __restrict__ dstv, int* __restrict__ cnt)
{
    int e = blockIdx.x * blockDim.x + threadIdx.x;
    if (e >= E_TR) return;
    int s = ei[e];
    int d = ei[E_TR + e];
    int t = et[e];
    ssel[e] = s + t * NNODES;
    dstv[e] = d;
    atomicAdd(&cnt[d], 1);
}

__global__ void scan1_k(const int* __restrict__ cnt, int* __restrict__ pre, int* __restrict__ bsum)
{
    __shared__ int sh[256];
    int tid = threadIdx.x;
    int base = blockIdx.x * 1024 + tid * 4;
    int v[4];
#pragma unroll
    for (int j = 0; j < 4; j++) v[j] = (base + j < NNODES) ? cnt[base + j] : 0;
    int tsum = v[0] + v[1] + v[2] + v[3];
    sh[tid] = tsum;
    __syncthreads();
    for (int off = 1; off < 256; off <<= 1) {
        int t = (tid >= off) ? sh[tid - off] : 0;
        __syncthreads();
        sh[tid] += t;
        __syncthreads();
    }
    int run = sh[tid] - tsum;
#pragma unroll
    for (int j = 0; j < 4; j++) {
        if (base + j < NNODES) pre[base + j] = run;
        run += v[j];
    }
    if (tid == 255) bsum[blockIdx.x] = sh[255];
}

__global__ void scan2_k(int* __restrict__ bsum, int nb)
{
    __shared__ int sh[256];
    int tid = threadIdx.x;
    int v = (tid < nb) ? bsum[tid] : 0;
    sh[tid] = v;
    __syncthreads();
    for (int off = 1; off < 256; off <<= 1) {
        int t = (tid >= off) ? sh[tid - off] : 0;
        __syncthreads();
        sh[tid] += t;
        __syncthreads();
    }
    if (tid < nb) bsum[tid] = sh[tid] - v;
}

__global__ void scan3_k(const int* __restrict__ pre, const int* __restrict__ bsum,
                        int* __restrict__ rowptr, int* __restrict__ cursor)
{
    int n = blockIdx.x * blockDim.x + threadIdx.x;
    if (n >= NNODES) return;
    int rp = pre[n] + bsum[n >> 10];
    rowptr[n] = rp;
    cursor[n] = rp;
}

__global__ void scatter_k(const int* __restrict__ ssel, const int* __restrict__ dstv,
                          int* __restrict__ cursor, int* __restrict__ eidx)
{
    int e = blockIdx.x * blockDim.x + threadIdx.x;
    if (e >= E_TR) return;
    int pos = atomicAdd(&cursor[dstv[e]], 1);
    eidx[pos] = ssel[e];
}

// ---- encode: row-per-thread, smem-staged x tiles, broadcast W reads, FFMA2 ----
// out[row, 0:16] = x[row, 0:DIN] @ W[DIN,16] + b
// x tile: 128 rows x 64 k, stride 65 -> conflict-free store (coalesced gmem) and
// conflict-free read (bank = (tid + k) % 32). W reads are warp-broadcast LDS.128.
template<int DIN>
__global__ void __launch_bounds__(128) encode_k(const float* __restrict__ x,
                                                const float* __restrict__ W,
                                                const float* __restrict__ b,
                                                float* __restrict__ out, int nrows)
{
    constexpr int KC = 64;
    constexpr int NCHUNK = DIN / KC;
    __shared__ float xt[128 * 65];
    __shared__ ulonglong2 Wp[DIN * 4];     // [k][4] : 16 outputs as 4x(u64 pair)
    __shared__ float bs[16];
    const ulonglong2* Wg = (const ulonglong2*)W;
    for (int i = threadIdx.x; i < DIN * 4; i += 128) Wp[i] = Wg[i];
    if (threadIdx.x < 16) bs[threadIdx.x] = b[threadIdx.x];

    int tid = threadIdx.x;
    int rowBase = blockIdx.x * 128;
    int row = rowBase + tid;
    bool valid = (row < nrows);

    u64 acc[8];
#pragma unroll
    for (int p = 0; p < 8; p++) acc[p] = 0ull;

    for (int ch = 0; ch < NCHUNK; ch++) {
        __syncthreads();
        // cooperative tile load: 128 rows x 64 cols, coalesced on gmem
        for (int i = tid; i < 128 * KC; i += 128) {
            int r = i >> 6;           // /KC
            int c = i & (KC - 1);
            int gr = rowBase + r;
            float v = (gr < nrows) ? x[(size_t)gr * DIN + ch * KC + c] : 0.f;
            xt[r * 65 + c] = v;
        }
        __syncthreads();
#pragma unroll
        for (int k = 0; k < KC; k++) {
            float xv = xt[tid * 65 + k];
            u64 xx = pack2(xv, xv);
            int kb = (ch * KC + k) * 4;
#pragma unroll
            for (int q = 0; q < 4; q++) {
                ulonglong2 w = Wp[kb + q];
                acc[2 * q]     = ffma2(xx, w.x, acc[2 * q]);
                acc[2 * q + 1] = ffma2(xx, w.y, acc[2 * q + 1]);
            }
        }
    }
    if (!valid) return;
    float4* op = (float4*)(out + (size_t)row * 16);
#pragma unroll
    for (int q = 0; q < 4; q++) {
        float2 lo = unpack2(acc[2 * q]);
        float2 hi = unpack2(acc[2 * q + 1]);
        op[q] = make_float4(lo.x + bs[4 * q], lo.y + bs[4 * q + 1],
                            hi.x + bs[4 * q + 2], hi.y + bs[4 * q + 3]);
    }
}

// ---- fused node transform: Y0, Y1, self in one pass; broadcast LDS.128 W reads ----
template<int DIN, int DOUT>
__global__ void __launch_bounds__(256) transform3_k(const float* __restrict__ xin,
                                                    const float* __restrict__ Wpair,
                                                    const float* __restrict__ root,
                                                    const float* __restrict__ bias,
                                                    float* __restrict__ Ycat,
                                                    float* __restrict__ selfout)
{
    constexpr int DO2 = DOUT / 2;
    constexpr int DO4 = DOUT / 4;
    __shared__ ulonglong2 Ws4[3 * DIN * DO4];
    __shared__ u64 bs2[DO2];
    const u64* Wg = (const u64*)Wpair;
    const u64* Rg = (const u64*)root;
    u64* Wsu = (u64*)Ws4;
    for (int i = threadIdx.x; i < 2 * DIN * DO2; i += blockDim.x) Wsu[i] = Wg[i];
    for (int i = threadIdx.x; i < DIN * DO2; i += blockDim.x) Wsu[2 * DIN * DO2 + i] = Rg[i];
    if (threadIdx.x < DO2) bs2[threadIdx.x] = ((const u64*)bias)[threadIdx.x];
    __syncthreads();
    int row = blockIdx.x * blockDim.x + threadIdx.x;
    if (row >= NNODES) return;
    float xr[DIN];
    const float4* xp = (const float4*)(xin + (size_t)row * DIN);
#pragma unroll
    for (int k4 = 0; k4 < DIN / 4; k4++) {
        float4 v = xp[k4];
        xr[4*k4] = v.x; xr[4*k4+1] = v.y; xr[4*k4+2] = v.z; xr[4*k4+3] = v.w;
    }
    u64 a0[DO2], a1[DO2], a2[DO2];
#pragma unroll
    for (int p = 0; p < DO2; p++) { a0[p] = 0ull; a1[p] = 0ull; a2[p] = bs2[p]; }
#pragma unroll
    for (int k = 0; k < DIN; k++) {
        u64 xx = pack2(xr[k], xr[k]);
#pragma unroll
        for (int o = 0; o < DO4; o++) {
            ulonglong2 w0 = Ws4[k * DO4 + o];
            a0[2*o]   = ffma2(xx, w0.x, a0[2*o]);
            a0[2*o+1] = ffma2(xx, w0.y, a0[2*o+1]);
            ulonglong2 w1 = Ws4[(DIN + k) * DO4 + o];
            a1[2*o]   = ffma2(xx, w1.x, a1[2*o]);
            a1[2*o+1] = ffma2(xx, w1.y, a1[2*o+1]);
            ulonglong2 w2 = Ws4[(2 * DIN + k) * DO4 + o];
            a2[2*o]   = ffma2(xx, w2.x, a2[2*o]);
            a2[2*o+1] = ffma2(xx, w2.y, a2[2*o+1]);
        }
    }
    float4* y0 = (float4*)(Ycat + (size_t)row * DOUT);
    float4* y1 = (float4*)(Ycat + (size_t)(NNODES + row) * DOUT);
    float4* sf = (float4*)(selfout + (size_t)row * DOUT);
#pragma unroll
    for (int o = 0; o < DO4; o++) {
        float2 l0 = unpack2(a0[2*o]), h0 = unpack2(a0[2*o+1]);
        y0[o] = make_float4(l0.x, l0.y, h0.x, h0.y);
        float2 l1 = unpack2(a1[2*o]), h1 = unpack2(a1[2*o+1]);
        y1[o] = make_float4(l1.x, l1.y, h1.x, h1.y);
        float2 l2 = unpack2(a2[2*o]), h2 = unpack2(a2[2*o+1]);
        sf[o] = make_float4(l2.x, l2.y, h2.x, h2.y);
    }
}

// ---- CSR gather aggregation + fused finalize ----
template<int DOUT, bool RELU>
__global__ void __launch_bounds__(256) agg_csr_k(const int* __restrict__ rowptr,
                                                 const int* __restrict__ cnt,
                                                 const int* __restrict__ eidx,
                                                 const float* __restrict__ Y,
                                                 float* __restrict__ x)
{
    constexpr int DO4 = DOUT / 4;
    int gid = blockIdx.x * blockDim.x + threadIdx.x;
    int n = gid / DO4;
    int j = gid % DO4;
    if (n >= NNODES) return;
    int start = rowptr[n];
    int deg = cnt[n];
    const float4* Y4 = (const float4*)Y;
    float4 acc = make_float4(0.f, 0.f, 0.f, 0.f);
    int k = 0;
    for (; k + 2 <= deg; k += 2) {
        int r0 = eidx[start + k];
        int r1 = eidx[start + k + 1];
        float4 v0 = Y4[(size_t)r0 * DO4 + j];
        float4 v1 = Y4[(size_t)r1 * DO4 + j];
        acc.x += v0.x + v1.x; acc.y += v0.y + v1.y;
        acc.z += v0.z + v1.z; acc.w += v0.w + v1.w;
    }
    if (k < deg) {
        int r = eidx[start + k];
        float4 v = Y4[(size_t)r * DO4 + j];
        acc.x += v.x; acc.y += v.y; acc.z += v.z; acc.w += v.w;
    }
    float s = 1.0f / fmaxf((float)deg, 1.0f);
    float4* xp = (float4*)x + (size_t)n * DO4 + j;
    float4 v = *xp;
    v.x += acc.x * s; v.y += acc.y * s; v.z += acc.z * s; v.w += acc.w * s;
    if (RELU) {
        v.x = fmaxf(v.x, 0.f); v.y = fmaxf(v.y, 0.f);
        v.z = fmaxf(v.z, 0.f); v.w = fmaxf(v.w, 0.f);
    }
    *xp = v;
}

// ---- decode ----
__global__ void __launch_bounds__(256) decode_k(const int* __restrict__ ei,
                                                const int* __restrict__ et,
                                                const float* __restrict__ z,
                                                const float* __restrict__ w0, const float* __restrict__ b0,
                                                const float* __restrict__ w1, const float* __restrict__ b1,
                                                float* __restrict__ out, int E)
{
    __shared__ float4 Ws[128];   // [2][16][4]
    __shared__ float bs[32];
    for (int i = threadIdx.x; i < 128; i += blockDim.x)
        Ws[i] = (i < 64) ? ((const float4*)w0)[i] : ((const float4*)w1)[i - 64];
    if (threadIdx.x < 32)
        bs[threadIdx.x] = (threadIdx.x < 16) ? b0[threadIdx.x] : b1[threadIdx.x - 16];
    __syncthreads();
    int e = blockIdx.x * blockDim.x + threadIdx.x;
    if (e >= E) return;
    int s = ei[e];
    int d = ei[E + e];
    int t = et[e];
    const float4* zs4 = (const float4*)(z + (size_t)s * 16);
    const float4* zd4 = (const float4*)(z + (size_t)d * 16);
    float zs[16];
#pragma unroll
    for (int k4 = 0; k4 < 4; k4++) {
        float4 v = zs4[k4];
        zs[4*k4] = v.x; zs[4*k4+1] = v.y; zs[4*k4+2] = v.z; zs[4*k4+3] = v.w;
    }
    float4 zd[4];
#pragma unroll
    for (int k4 = 0; k4 < 4; k4++) zd[k4] = zd4[k4];
    int tb = t * 16;
    float4 acc[4];
#pragma unroll
    for (int o = 0; o < 4; o++) acc[o] = make_float4(bs[tb+4*o], bs[tb+4*o+1], bs[tb+4*o+2], bs[tb+4*o+3]);
#pragma unroll
    for (int k = 0; k < 16; k++) {
        float xv = zs[k];
#pragma unroll
        for (int o = 0; o < 4; o++) {
            float4 w = Ws[t * 64 + k * 4 + o];
            acc[o].x += xv * w.x; acc[o].y += xv * w.y;
            acc[o].z += xv * w.z; acc[o].w += xv * w.w;
        }
    }
    float sc = 0.f;
#pragma unroll
    for (int o = 0; o < 4; o++)
        sc += acc[o].x*zd[o].x + acc[o].y*zd[o].y + acc[o].z*zd[o].z + acc[o].w*zd[o].w;
    out[e] = sc;
}

extern "C" void kernel_launch(void* const* d_in, const int* in_sizes, int n_in,
                              void* d_out, int out_size)
{
    const float* x_paper = (const float*)d_in[0];
    const float* x_mesh  = (const float*)d_in[1];
    const float* tp_w = (const float*)d_in[2];
    const float* tp_b = (const float*)d_in[3];
    const float* tm_w = (const float*)d_in[4];
    const float* tm_b = (const float*)d_in[5];
    const float* comp1 = (const float*)d_in[6];
    const float* basis1 = (const float*)d_in[7];
    const float* root1 = (const float*)d_in[8];
    const float* bias1 = (const float*)d_in[9];
    const float* comp2 = (const float*)d_in[10];
    const float* basis2 = (const float*)d_in[11];
    const float* root2 = (const float*)d_in[12];
    const float* bias2 = (const float*)d_in[13];
    const float* comp3 = (const float*)d_in[14];
    const float* basis3 = (const float*)d_in[15];
    const float* root3 = (const float*)d_in[16];
    const float* bias3 = (const float*)d_in[17];
    const float* dpp_w = (const float*)d_in[18];
    const float* dpp_b = (const float*)d_in[19];
    const float* dpm_w = (const float*)d_in[20];
    const float* dpm_b = (const float*)d_in[21];
    const int* tei = (const int*)d_in[22];   // JAX x32: int32 arrays
    const int* tet = (const int*)d_in[23];
    const int* pei = (const int*)d_in[24];
    const int* pet = (const int*)d_in[25];
    const int* nei = (const int*)d_in[26];
    const int* net = (const int*)d_in[27];
    float* out = (float*)d_out;

    float *x0, *x1, *Y, *W;
    int *ssel, *dstv, *eidx, *cnt, *rowptr, *cursor, *pre, *bsum;
    cudaGetSymbolAddress((void**)&x0, g_x0);
    cudaGetSymbolAddress((void**)&x1, g_x1);
    cudaGetSymbolAddress((void**)&Y, g_Y);
    cudaGetSymbolAddress((void**)&W, g_W);
    cudaGetSymbolAddress((void**)&ssel, g_ssel);
    cudaGetSymbolAddress((void**)&dstv, g_dst);
    cudaGetSymbolAddress((void**)&eidx, g_eidx);
    cudaGetSymbolAddress((void**)&cnt, g_cnt);
    cudaGetSymbolAddress((void**)&rowptr, g_rowptr);
    cudaGetSymbolAddress((void**)&cursor, g_cursor);
    cudaGetSymbolAddress((void**)&pre, g_pre);
    cudaGetSymbolAddress((void**)&bsum, g_bsum);

    const int EB = (E_TR + 255) / 256;
    const int NB = (NNODES + 255) / 256;

    // Launch order note: ncu in this harness captures the 5th graph node;
    // encode_k<512> is placed 5th (deps allow it — it's independent of CSR).
    cudaMemsetAsync(cnt, 0, NNODES * sizeof(int));                       // 1
    hist_k<<<EB, 256>>>(tei, tet, ssel, dstv, cnt);                      // 2
    scan1_k<<<NBLK_SCAN, 256>>>(cnt, pre, bsum);                         // 3
    scan2_k<<<1, 256>>>(bsum, NBLK_SCAN);                                // 4
    encode_k<512><<<(N_PAPER + 127) / 128, 128>>>(x_paper, tp_w, tp_b, x0, N_PAPER);  // 5 <- profiled
    encode_k<128><<<(N_MESH + 127) / 128, 128>>>(x_mesh, tm_w, tm_b,
                                                 x0 + (size_t)N_PAPER * 16, N_MESH);  // 6
    scan3_k<<<NB, 256>>>(pre, bsum, rowptr, cursor);                     // 7
    scatter_k<<<EB, 256>>>(ssel, dstv, cursor, eidx);                    // 8

    // ---- layer 1: 16 -> 32, relu ----
    make_W_k<<<8, 256>>>(comp1, basis1, W, 16 * 32);
    transform3_k<16, 32><<<NB, 256>>>(x0, W, root1, bias1, Y, x1);
    agg_csr_k<32, true><<<(NNODES * 8 + 255) / 256, 256>>>(rowptr, cnt, eidx, Y, x1);

    // ---- layer 2: 32 -> 32, relu ----
    make_W_k<<<8, 256>>>(comp2, basis2, W, 32 * 32);
    transform3_k<32, 32><<<NB, 256>>>(x1, W, root2, bias2, Y, x0);
    agg_csr_k<32, true><<<(NNODES * 8 + 255) / 256, 256>>>(rowptr, cnt, eidx, Y, x0);

    // ---- layer 3: 32 -> 16, no relu -> z in x1 ----
    make_W_k<<<8, 256>>>(comp3, basis3, W, 32 * 16);
    transform3_k<32, 16><<<NB, 256>>>(x0, W, root3, bias3, Y, x1);
    agg_csr_k<16, false><<<(NNODES * 4 + 255) / 256, 256>>>(rowptr, cnt, eidx, Y, x1);

    // ---- decode: pos then neg ----
    decode_k<<<(E_P + 255) / 256, 256>>>(pei, pet, x1, dpp_w, dpp_b, dpm_w, dpm_b, out, E_P);
    decode_k<<<(E_N + 255) / 256, 256>>>(nei, net, x1, dpp_w, dpp_b, dpm_w, dpm_b, out + E_P, E_N);
}

// round 7
// speedup vs baseline: 1.2934x; 1.2934x over previous
#include <cuda_runtime.h>

static const int N_PAPER = 200000;
static const int N_MESH  = 30000;
static const int NNODES  = 230000;
static const int E_TR    = 2000000;
static const int E_P     = 500000;
static const int E_N     = 500000;
static const int NBLK_SCAN = (NNODES + 1023) / 1024;   // 225

typedef unsigned long long u64;

// ---- static device scratch ----
__device__ __align__(256) float g_x0[NNODES * 32];
__device__ __align__(256) float g_x1[NNODES * 32];
__device__ __align__(256) float g_Y[2 * NNODES * 32];   // [Y_rel0 ; Y_rel1]
__device__ __align__(256) int   g_ssel[E_TR];           // src + etype*NNODES
__device__ __align__(256) int   g_dst[E_TR];
__device__ __align__(256) int   g_eidx[E_TR];           // CSR buckets (ssel by dst)
__device__ __align__(256) int   g_cnt[NNODES];
__device__ __align__(256) int   g_rowptr[NNODES];
__device__ __align__(256) int   g_cursor[NNODES];
__device__ __align__(256) int   g_pre[NNODES];
__device__ __align__(256) int   g_bsum[NBLK_SCAN];
__device__ __align__(256) float g_W[2 * 32 * 32];

// ---- packed f32x2 helpers (FFMA2 is PTX-only) ----
__device__ __forceinline__ u64 pack2(float a, float b) {
    u64 r;
    asm("mov.b64 %0, {%1, %2};" : "=l"(r) : "r"(__float_as_uint(a)), "r"(__float_as_uint(b)));
    return r;
}
__device__ __forceinline__ u64 ffma2(u64 a, u64 b, u64 c) {
    u64 d;
    asm("fma.rn.f32x2 %0, %1, %2, %3;" : "=l"(d) : "l"(a), "l"(b), "l"(c));
    return d;
}
__device__ __forceinline__ float2 unpack2(u64 v) {
    unsigned lo, hi;
    asm("mov.b64 {%0, %1}, %2;" : "=r"(lo), "=r"(hi) : "l"(v));
    return make_float2(__uint_as_float(lo), __uint_as_float(hi));
}

// W[r] = sum_b comp[r,b] * basis[b]
__global__ void make_W_k(const float* __restrict__ comp, const float* __restrict__ basis,
                         float* __restrict__ W, int dio)
{
    int tot = 2 * dio;
    for (int i = blockIdx.x * blockDim.x + threadIdx.x; i < tot; i += gridDim.x * blockDim.x) {
        int r = i / dio, io = i % dio;
        float s = 0.f;
#pragma unroll
        for (int b = 0; b < 4; b++) s += comp[r * 4 + b] * basis[b * dio + io];
        W[i] = s;
    }
}

// ---- CSR build ----
__global__ void hist_k(const int* __restrict__ ei, const int* __restrict__ et,
                       int* __restrict__ ssel, int* __restrict__ dstv, int* __restrict__ cnt)
{
    int e = blockIdx.x * blockDim.x + threadIdx.x;
    if (e >= E_TR) return;
    int s = ei[e];
    int d = ei[E_TR + e];
    int t = et[e];
    ssel[e] = s + t * NNODES;
    dstv[e] = d;
    atomicAdd(&cnt[d], 1);
}

__global__ void scan1_k(const int* __restrict__ cnt, int* __restrict__ pre, int* __restrict__ bsum)
{
    __shared__ int sh[256];
    int tid = threadIdx.x;
    int base = blockIdx.x * 1024 + tid * 4;
    int v[4];
#pragma unroll
    for (int j = 0; j < 4; j++) v[j] = (base + j < NNODES) ? cnt[base + j] : 0;
    int tsum = v[0] + v[1] + v[2] + v[3];
    sh[tid] = tsum;
    __syncthreads();
    for (int off = 1; off < 256; off <<= 1) {
        int t = (tid >= off) ? sh[tid - off] : 0;
        __syncthreads();
        sh[tid] += t;
        __syncthreads();
    }
    int run = sh[tid] - tsum;
#pragma unroll
    for (int j = 0; j < 4; j++) {
        if (base + j < NNODES) pre[base + j] = run;
        run += v[j];
    }
    if (tid == 255) bsum[blockIdx.x] = sh[255];
}

__global__ void scan2_k(int* __restrict__ bsum, int nb)
{
    __shared__ int sh[256];
    int tid = threadIdx.x;
    int v = (tid < nb) ? bsum[tid] : 0;
    sh[tid] = v;
    __syncthreads();
    for (int off = 1; off < 256; off <<= 1) {
        int t = (tid >= off) ? sh[tid - off] : 0;
        __syncthreads();
        sh[tid] += t;
        __syncthreads();
    }
    if (tid < nb) bsum[tid] = sh[tid] - v;
}

__global__ void scan3_k(const int* __restrict__ pre, const int* __restrict__ bsum,
                        int* __restrict__ rowptr, int* __restrict__ cursor)
{
    int n = blockIdx.x * blockDim.x + threadIdx.x;
    if (n >= NNODES) return;
    int rp = pre[n] + bsum[n >> 10];
    rowptr[n] = rp;
    cursor[n] = rp;
}

__global__ void scatter_k(const int* __restrict__ ssel, const int* __restrict__ dstv,
                          int* __restrict__ cursor, int* __restrict__ eidx)
{
    int e = blockIdx.x * blockDim.x + threadIdx.x;
    if (e >= E_TR) return;
    int pos = atomicAdd(&cursor[dstv[e]], 1);
    eidx[pos] = ssel[e];
}

// ---- encode: row-per-thread, chunked k=32 staging, high occupancy ----
// out[row, 0:16] = x[row, 0:DIN] @ W[DIN,16] + b
// smem: x tile 256 rows x 32 k (pad 33 -> conflict-free: bank=(t+k)%32),
//       W chunk 32 rows x 16 outs (2KB, warp-uniform broadcast reads).
template<int DIN>
__global__ void __launch_bounds__(256) encode_k(const float* __restrict__ x,
                                                const float* __restrict__ W,
                                                const float* __restrict__ b,
                                                float* __restrict__ out, int nrows)
{
    constexpr int KC = 32;
    constexpr int NCHUNK = DIN / KC;
    __shared__ float xt[256 * 33];
    __shared__ ulonglong2 Wc[KC * 4];   // current W chunk: [32 k][4 pairs-of-2]
    __shared__ float bs[16];
    const ulonglong2* Wg = (const ulonglong2*)W;
    if (threadIdx.x < 16) bs[threadIdx.x] = b[threadIdx.x];

    int tid = threadIdx.x;
    int rowBase = blockIdx.x * 256;
    int row = rowBase + tid;

    u64 acc[8];
#pragma unroll
    for (int p = 0; p < 8; p++) acc[p] = 0ull;

    for (int ch = 0; ch < NCHUNK; ch++) {
        __syncthreads();
        // W chunk: 32 k * 4 ulonglong2 = 128 entries, tid < 128 loads one
        if (tid < KC * 4) Wc[tid] = Wg[(size_t)(ch * KC) * 4 + tid];
        // x tile: 256 rows x 32 cols, scalar loads, fully coalesced
#pragma unroll
        for (int it = 0; it < 32; it++) {
            int idx = it * 256 + tid;
            int r = idx >> 5;
            int c = idx & 31;
            int gr = rowBase + r;
            float v = (gr < nrows) ? x[(size_t)gr * DIN + ch * KC + c] : 0.f;
            xt[r * 33 + c] = v;
        }
        __syncthreads();
#pragma unroll
        for (int k = 0; k < KC; k++) {
            float xv = xt[tid * 33 + k];
            u64 xx = pack2(xv, xv);
#pragma unroll
            for (int q = 0; q < 4; q++) {
                ulonglong2 w = Wc[k * 4 + q];
                acc[2 * q]     = ffma2(xx, w.x, acc[2 * q]);
                acc[2 * q + 1] = ffma2(xx, w.y, acc[2 * q + 1]);
            }
        }
    }
    if (row >= nrows) return;
    float4* op = (float4*)(out + (size_t)row * 16);
#pragma unroll
    for (int q = 0; q < 4; q++) {
        float2 lo = unpack2(acc[2 * q]);
        float2 hi = unpack2(acc[2 * q + 1]);
        op[q] = make_float4(lo.x + bs[4 * q], lo.y + bs[4 * q + 1],
                            hi.x + bs[4 * q + 2], hi.y + bs[4 * q + 3]);
    }
}

// ---- fused node transform: Y0, Y1, self in one pass; broadcast LDS.128 W reads ----
template<int DIN, int DOUT>
__global__ void __launch_bounds__(256) transform3_k(const float* __restrict__ xin,
                                                    const float* __restrict__ Wpair,
                                                    const float* __restrict__ root,
                                                    const float* __restrict__ bias,
                                                    float* __restrict__ Ycat,
                                                    float* __restrict__ selfout)
{
    constexpr int DO2 = DOUT / 2;
    constexpr int DO4 = DOUT / 4;
    __shared__ ulonglong2 Ws4[3 * DIN * DO4];
    __shared__ u64 bs2[DO2];
    const u64* Wg = (const u64*)Wpair;
    const u64* Rg = (const u64*)root;
    u64* Wsu = (u64*)Ws4;
    for (int i = threadIdx.x; i < 2 * DIN * DO2; i += blockDim.x) Wsu[i] = Wg[i];
    for (int i = threadIdx.x; i < DIN * DO2; i += blockDim.x) Wsu[2 * DIN * DO2 + i] = Rg[i];
    if (threadIdx.x < DO2) bs2[threadIdx.x] = ((const u64*)bias)[threadIdx.x];
    __syncthreads();
    int row = blockIdx.x * blockDim.x + threadIdx.x;
    if (row >= NNODES) return;
    float xr[DIN];
    const float4* xp = (const float4*)(xin + (size_t)row * DIN);
#pragma unroll
    for (int k4 = 0; k4 < DIN / 4; k4++) {
        float4 v = xp[k4];
        xr[4*k4] = v.x; xr[4*k4+1] = v.y; xr[4*k4+2] = v.z; xr[4*k4+3] = v.w;
    }
    u64 a0[DO2], a1[DO2], a2[DO2];
#pragma unroll
    for (int p = 0; p < DO2; p++) { a0[p] = 0ull; a1[p] = 0ull; a2[p] = bs2[p]; }
#pragma unroll
    for (int k = 0; k < DIN; k++) {
        u64 xx = pack2(xr[k], xr[k]);
#pragma unroll
        for (int o = 0; o < DO4; o++) {
            ulonglong2 w0 = Ws4[k * DO4 + o];
            a0[2*o]   = ffma2(xx, w0.x, a0[2*o]);
            a0[2*o+1] = ffma2(xx, w0.y, a0[2*o+1]);
            ulonglong2 w1 = Ws4[(DIN + k) * DO4 + o];
            a1[2*o]   = ffma2(xx, w1.x, a1[2*o]);
            a1[2*o+1] = ffma2(xx, w1.y, a1[2*o+1]);
            ulonglong2 w2 = Ws4[(2 * DIN + k) * DO4 + o];
            a2[2*o]   = ffma2(xx, w2.x, a2[2*o]);
            a2[2*o+1] = ffma2(xx, w2.y, a2[2*o+1]);
        }
    }
    float4* y0 = (float4*)(Ycat + (size_t)row * DOUT);
    float4* y1 = (float4*)(Ycat + (size_t)(NNODES + row) * DOUT);
    float4* sf = (float4*)(selfout + (size_t)row * DOUT);
#pragma unroll
    for (int o = 0; o < DO4; o++) {
        float2 l0 = unpack2(a0[2*o]), h0 = unpack2(a0[2*o+1]);
        y0[o] = make_float4(l0.x, l0.y, h0.x, h0.y);
        float2 l1 = unpack2(a1[2*o]), h1 = unpack2(a1[2*o+1]);
        y1[o] = make_float4(l1.x, l1.y, h1.x, h1.y);
        float2 l2 = unpack2(a2[2*o]), h2 = unpack2(a2[2*o+1]);
        sf[o] = make_float4(l2.x, l2.y, h2.x, h2.y);
    }
}

// ---- CSR gather aggregation + fused finalize ----
template<int DOUT, bool RELU>
__global__ void __launch_bounds__(256) agg_csr_k(const int* __restrict__ rowptr,
                                                 const int* __restrict__ cnt,
                                                 const int* __restrict__ eidx,
                                                 const float* __restrict__ Y,
                                                 float* __restrict__ x)
{
    constexpr int DO4 = DOUT / 4;
    int gid = blockIdx.x * blockDim.x + threadIdx.x;
    int n = gid / DO4;
    int j = gid % DO4;
    if (n >= NNODES) return;
    int start = rowptr[n];
    int deg = cnt[n];
    const float4* Y4 = (const float4*)Y;
    float4 acc = make_float4(0.f, 0.f, 0.f, 0.f);
    int k = 0;
    for (; k + 2 <= deg; k += 2) {
        int r0 = eidx[start + k];
        int r1 = eidx[start + k + 1];
        float4 v0 = Y4[(size_t)r0 * DO4 + j];
        float4 v1 = Y4[(size_t)r1 * DO4 + j];
        acc.x += v0.x + v1.x; acc.y += v0.y + v1.y;
        acc.z += v0.z + v1.z; acc.w += v0.w + v1.w;
    }
    if (k < deg) {
        int r = eidx[start + k];
        float4 v = Y4[(size_t)r * DO4 + j];
        acc.x += v.x; acc.y += v.y; acc.z += v.z; acc.w += v.w;
    }
    float s = 1.0f / fmaxf((float)deg, 1.0f);
    float4* xp = (float4*)x + (size_t)n * DO4 + j;
    float4 v = *xp;
    v.x += acc.x * s; v.y += acc.y * s; v.z += acc.z * s; v.w += acc.w * s;
    if (RELU) {
        v.x = fmaxf(v.x, 0.f); v.y = fmaxf(v.y, 0.f);
        v.z = fmaxf(v.z, 0.f); v.w = fmaxf(v.w, 0.f);
    }
    *xp = v;
}

// ---- decode ----
__global__ void __launch_bounds__(256) decode_k(const int* __restrict__ ei,
                                                const int* __restrict__ et,
                                                const float* __restrict__ z,
                                                const float* __restrict__ w0, const float* __restrict__ b0,
                                                const float* __restrict__ w1, const float* __restrict__ b1,
                                                float* __restrict__ out, int E)
{
    __shared__ float4 Ws[128];   // [2][16][4]
    __shared__ float bs[32];
    for (int i = threadIdx.x; i < 128; i += blockDim.x)
        Ws[i] = (i < 64) ? ((const float4*)w0)[i] : ((const float4*)w1)[i - 64];
    if (threadIdx.x < 32)
        bs[threadIdx.x] = (threadIdx.x < 16) ? b0[threadIdx.x] : b1[threadIdx.x - 16];
    __syncthreads();
    int e = blockIdx.x * blockDim.x + threadIdx.x;
    if (e >= E) return;
    int s = ei[e];
    int d = ei[E + e];
    int t = et[e];
    const float4* zs4 = (const float4*)(z + (size_t)s * 16);
    const float4* zd4 = (const float4*)(z + (size_t)d * 16);
    float zs[16];
#pragma unroll
    for (int k4 = 0; k4 < 4; k4++) {
        float4 v = zs4[k4];
        zs[4*k4] = v.x; zs[4*k4+1] = v.y; zs[4*k4+2] = v.z; zs[4*k4+3] = v.w;
    }
    float4 zd[4];
#pragma unroll
    for (int k4 = 0; k4 < 4; k4++) zd[k4] = zd4[k4];
    int tb = t * 16;
    float4 acc[4];
#pragma unroll
    for (int o = 0; o < 4; o++) acc[o] = make_float4(bs[tb+4*o], bs[tb+4*o+1], bs[tb+4*o+2], bs[tb+4*o+3]);
#pragma unroll
    for (int k = 0; k < 16; k++) {
        float xv = zs[k];
#pragma unroll
        for (int o = 0; o < 4; o++) {
            float4 w = Ws[t * 64 + k * 4 + o];
            acc[o].x += xv * w.x; acc[o].y += xv * w.y;
            acc[o].z += xv * w.z; acc[o].w += xv * w.w;
        }
    }
    float sc = 0.f;
#pragma unroll
    for (int o = 0; o < 4; o++)
        sc += acc[o].x*zd[o].x + acc[o].y*zd[o].y + acc[o].z*zd[o].z + acc[o].w*zd[o].w;
    out[e] = sc;
}

extern "C" void kernel_launch(void* const* d_in, const int* in_sizes, int n_in,
                              void* d_out, int out_size)
{
    const float* x_paper = (const float*)d_in[0];
    const float* x_mesh  = (const float*)d_in[1];
    const float* tp_w = (const float*)d_in[2];
    const float* tp_b = (const float*)d_in[3];
    const float* tm_w = (const float*)d_in[4];
    const float* tm_b = (const float*)d_in[5];
    const float* comp1 = (const float*)d_in[6];
    const float* basis1 = (const float*)d_in[7];
    const float* root1 = (const float*)d_in[8];
    const float* bias1 = (const float*)d_in[9];
    const float* comp2 = (const float*)d_in[10];
    const float* basis2 = (const float*)d_in[11];
    const float* root2 = (const float*)d_in[12];
    const float* bias2 = (const float*)d_in[13];
    const float* comp3 = (const float*)d_in[14];
    const float* basis3 = (const float*)d_in[15];
    const float* root3 = (const float*)d_in[16];
    const float* bias3 = (const float*)d_in[17];
    const float* dpp_w = (const float*)d_in[18];
    const float* dpp_b = (const float*)d_in[19];
    const float* dpm_w = (const float*)d_in[20];
    const float* dpm_b = (const float*)d_in[21];
    const int* tei = (const int*)d_in[22];   // JAX x32: int32 arrays
    const int* tet = (const int*)d_in[23];
    const int* pei = (const int*)d_in[24];
    const int* pet = (const int*)d_in[25];
    const int* nei = (const int*)d_in[26];
    const int* net = (const int*)d_in[27];
    float* out = (float*)d_out;

    float *x0, *x1, *Y, *W;
    int *ssel, *dstv, *eidx, *cnt, *rowptr, *cursor, *pre, *bsum;
    cudaGetSymbolAddress((void**)&x0, g_x0);
    cudaGetSymbolAddress((void**)&x1, g_x1);
    cudaGetSymbolAddress((void**)&Y, g_Y);
    cudaGetSymbolAddress((void**)&W, g_W);
    cudaGetSymbolAddress((void**)&ssel, g_ssel);
    cudaGetSymbolAddress((void**)&dstv, g_dst);
    cudaGetSymbolAddress((void**)&eidx, g_eidx);
    cudaGetSymbolAddress((void**)&cnt, g_cnt);
    cudaGetSymbolAddress((void**)&rowptr, g_rowptr);
    cudaGetSymbolAddress((void**)&cursor, g_cursor);
    cudaGetSymbolAddress((void**)&pre, g_pre);
    cudaGetSymbolAddress((void**)&bsum, g_bsum);

    const int EB = (E_TR + 255) / 256;
    const int NB = (NNODES + 255) / 256;

    // ncu captures the 5th graph node -> keep encode_k<512> there.
    cudaMemsetAsync(cnt, 0, NNODES * sizeof(int));                       // 1
    hist_k<<<EB, 256>>>(tei, tet, ssel, dstv, cnt);                      // 2
    scan1_k<<<NBLK_SCAN, 256>>>(cnt, pre, bsum);                         // 3
    scan2_k<<<1, 256>>>(bsum, NBLK_SCAN);                                // 4
    encode_k<512><<<(N_PAPER + 255) / 256, 256>>>(x_paper, tp_w, tp_b, x0, N_PAPER);  // 5 <- profiled
    encode_k<128><<<(N_MESH + 255) / 256, 256>>>(x_mesh, tm_w, tm_b,
                                                 x0 + (size_t)N_PAPER * 16, N_MESH);  // 6
    scan3_k<<<NB, 256>>>(pre, bsum, rowptr, cursor);                     // 7
    scatter_k<<<EB, 256>>>(ssel, dstv, cursor, eidx);                    // 8

    // ---- layer 1: 16 -> 32, relu ----
    make_W_k<<<8, 256>>>(comp1, basis1, W, 16 * 32);
    transform3_k<16, 32><<<NB, 256>>>(x0, W, root1, bias1, Y, x1);
    agg_csr_k<32, true><<<(NNODES * 8 + 255) / 256, 256>>>(rowptr, cnt, eidx, Y, x1);

    // ---- layer 2: 32 -> 32, relu ----
    make_W_k<<<8, 256>>>(comp2, basis2, W, 32 * 32);
    transform3_k<32, 32><<<NB, 256>>>(x1, W, root2, bias2, Y, x0);
    agg_csr_k<32, true><<<(NNODES * 8 + 255) / 256, 256>>>(rowptr, cnt, eidx, Y, x0);

    // ---- layer 3: 32 -> 16, no relu -> z in x1 ----
    make_W_k<<<8, 256>>>(comp3, basis3, W, 32 * 16);
    transform3_k<32, 16><<<NB, 256>>>(x0, W, root3, bias3, Y, x1);
    agg_csr_k<16, false><<<(NNODES * 4 + 255) / 256, 256>>>(rowptr, cnt, eidx, Y, x1);

    // ---- decode: pos then neg ----
    decode_k<<<(E_P + 255) / 256, 256>>>(pei, pet, x1, dpp_w, dpp_b, dpm_w, dpm_b, out, E_P);
    decode_k<<<(E_N + 255) / 256, 256>>>(nei, net, x1, dpp_w, dpp_b, dpm_w, dpm_b, out + E_P, E_N);
}

// round 8
// speedup vs baseline: 1.3891x; 1.0740x over previous
#include <cuda_runtime.h>

static const int N_PAPER = 200000;
static const int N_MESH  = 30000;
static const int NNODES  = 230000;
static const int E_TR    = 2000000;
static const int E_P     = 500000;
static const int E_N     = 500000;
static const int NBLK_SCAN = (NNODES + 1023) / 1024;   // 225

typedef unsigned long long u64;

// ---- static device scratch ----
__device__ __align__(256) float g_x0[NNODES * 32];
__device__ __align__(256) float g_x1[NNODES * 32];
__device__ __align__(256) float g_Y[2 * NNODES * 32];   // [Y_rel0 ; Y_rel1]
__device__ __align__(256) int   g_ssel[E_TR];           // src + etype*NNODES
__device__ __align__(256) int   g_dst[E_TR];
__device__ __align__(256) int   g_eidx[E_TR];           // CSR buckets (ssel by dst)
__device__ __align__(256) int   g_cnt[NNODES];
__device__ __align__(256) int   g_rowptr[NNODES];
__device__ __align__(256) int   g_cursor[NNODES];
__device__ __align__(256) int   g_pre[NNODES];
__device__ __align__(256) int   g_bsum[NBLK_SCAN];
__device__ __align__(256) float g_W[2 * 32 * 32];

// ---- packed f32x2 helpers (FFMA2 is PTX-only) ----
__device__ __forceinline__ u64 pack2(float a, float b) {
    u64 r;
    asm("mov.b64 %0, {%1, %2};" : "=l"(r) : "r"(__float_as_uint(a)), "r"(__float_as_uint(b)));
    return r;
}
__device__ __forceinline__ u64 ffma2(u64 a, u64 b, u64 c) {
    u64 d;
    asm("fma.rn.f32x2 %0, %1, %2, %3;" : "=l"(d) : "l"(a), "l"(b), "l"(c));
    return d;
}
__device__ __forceinline__ float2 unpack2(u64 v) {
    unsigned lo, hi;
    asm("mov.b64 {%0, %1}, %2;" : "=r"(lo), "=r"(hi) : "l"(v));
    return make_float2(__uint_as_float(lo), __uint_as_float(hi));
}

// W[r] = sum_b comp[r,b] * basis[b]
__global__ void make_W_k(const float* __restrict__ comp, const float* __restrict__ basis,
                         float* __restrict__ W, int dio)
{
    int tot = 2 * dio;
    for (int i = blockIdx.x * blockDim.x + threadIdx.x; i < tot; i += gridDim.x * blockDim.x) {
        int r = i / dio, io = i % dio;
        float s = 0.f;
#pragma unroll
        for (int b = 0; b < 4; b++) s += comp[r * 4 + b] * basis[b * dio + io];
        W[i] = s;
    }
}

// ---- CSR build ----
__global__ void hist_k(const int* __restrict__ ei, const int* __restrict__ et,
                       int* __restrict__ ssel, int* __restrict__ dstv, int* __restrict__ cnt)
{
    int e = blockIdx.x * blockDim.x + threadIdx.x;
    if (e >= E_TR) return;
    int s = ei[e];
    int d = ei[E_TR + e];
    int t = et[e];
    ssel[e] = s + t * NNODES;
    dstv[e] = d;
    atomicAdd(&cnt[d], 1);
}

__global__ void scan1_k(const int* __restrict__ cnt, int* __restrict__ pre, int* __restrict__ bsum)
{
    __shared__ int sh[256];
    int tid = threadIdx.x;
    int base = blockIdx.x * 1024 + tid * 4;
    int v[4];
#pragma unroll
    for (int j = 0; j < 4; j++) v[j] = (base + j < NNODES) ? cnt[base + j] : 0;
    int tsum = v[0] + v[1] + v[2] + v[3];
    sh[tid] = tsum;
    __syncthreads();
    for (int off = 1; off < 256; off <<= 1) {
        int t = (tid >= off) ? sh[tid - off] : 0;
        __syncthreads();
        sh[tid] += t;
        __syncthreads();
    }
    int run = sh[tid] - tsum;
#pragma unroll
    for (int j = 0; j < 4; j++) {
        if (base + j < NNODES) pre[base + j] = run;
        run += v[j];
    }
    if (tid == 255) bsum[blockIdx.x] = sh[255];
}

__global__ void scan2_k(int* __restrict__ bsum, int nb)
{
    __shared__ int sh[256];
    int tid = threadIdx.x;
    int v = (tid < nb) ? bsum[tid] : 0;
    sh[tid] = v;
    __syncthreads();
    for (int off = 1; off < 256; off <<= 1) {
        int t = (tid >= off) ? sh[tid - off] : 0;
        __syncthreads();
        sh[tid] += t;
        __syncthreads();
    }
    if (tid < nb) bsum[tid] = sh[tid] - v;
}

__global__ void scan3_k(const int* __restrict__ pre, const int* __restrict__ bsum,
                        int* __restrict__ rowptr, int* __restrict__ cursor)
{
    int n = blockIdx.x * blockDim.x + threadIdx.x;
    if (n >= NNODES) return;
    int rp = pre[n] + bsum[n >> 10];
    rowptr[n] = rp;
    cursor[n] = rp;
}

__global__ void scatter_k(const int* __restrict__ ssel, const int* __restrict__ dstv,
                          int* __restrict__ cursor, int* __restrict__ eidx)
{
    int e = blockIdx.x * blockDim.x + threadIdx.x;
    if (e >= E_TR) return;
    int pos = atomicAdd(&cursor[dstv[e]], 1);
    eidx[pos] = ssel[e];
}

// ---- encode: row-per-thread, chunked k=32 staging, occupancy-capped regs ----
// out[row, 0:16] = x[row, 0:DIN] @ W[DIN,16] + b
// __launch_bounds__(256, 4): regs <= 64 -> 4 CTAs/SM (smem 36KB x 4 = 145KB fits).
template<int DIN>
__global__ void __launch_bounds__(256, 4) encode_k(const float* __restrict__ x,
                                                   const float* __restrict__ W,
                                                   const float* __restrict__ b,
                                                   float* __restrict__ out, int nrows)
{
    constexpr int KC = 32;
    constexpr int NCHUNK = DIN / KC;
    __shared__ float xt[256 * 33];
    __shared__ ulonglong2 Wc[KC * 4];
    __shared__ float bs[16];
    const ulonglong2* Wg = (const ulonglong2*)W;
    if (threadIdx.x < 16) bs[threadIdx.x] = b[threadIdx.x];

    int tid = threadIdx.x;
    int rowBase = blockIdx.x * 256;
    int row = rowBase + tid;

    u64 acc[8];
#pragma unroll
    for (int p = 0; p < 8; p++) acc[p] = 0ull;

    for (int ch = 0; ch < NCHUNK; ch++) {
        __syncthreads();
        if (tid < KC * 4) Wc[tid] = Wg[(size_t)(ch * KC) * 4 + tid];
        // x tile: 256 rows x 32 cols; 4 groups of 8 unrolled loads (bounded temps)
        for (int g = 0; g < 4; g++) {
#pragma unroll
            for (int it = 0; it < 8; it++) {
                int idx = (g * 8 + it) * 256 + tid;
                int r = idx >> 5;
                int c = idx & 31;
                int gr = rowBase + r;
                float v = (gr < nrows) ? x[(size_t)gr * DIN + ch * KC + c] : 0.f;
                xt[r * 33 + c] = v;
            }
        }
        __syncthreads();
#pragma unroll
        for (int k = 0; k < KC; k++) {
            float xv = xt[tid * 33 + k];
            u64 xx = pack2(xv, xv);
#pragma unroll
            for (int q = 0; q < 4; q++) {
                ulonglong2 w = Wc[k * 4 + q];
                acc[2 * q]     = ffma2(xx, w.x, acc[2 * q]);
                acc[2 * q + 1] = ffma2(xx, w.y, acc[2 * q + 1]);
            }
        }
    }
    if (row >= nrows) return;
    float4* op = (float4*)(out + (size_t)row * 16);
#pragma unroll
    for (int q = 0; q < 4; q++) {
        float2 lo = unpack2(acc[2 * q]);
        float2 hi = unpack2(acc[2 * q + 1]);
        op[q] = make_float4(lo.x + bs[4 * q], lo.y + bs[4 * q + 1],
                            hi.x + bs[4 * q + 2], hi.y + bs[4 * q + 3]);
    }
}

// ---- fused node transform: Y0, Y1, self in one pass; broadcast LDS.128 W reads ----
template<int DIN, int DOUT>
__global__ void __launch_bounds__(256) transform3_k(const float* __restrict__ xin,
                                                    const float* __restrict__ Wpair,
                                                    const float* __restrict__ root,
                                                    const float* __restrict__ bias,
                                                    float* __restrict__ Ycat,
                                                    float* __restrict__ selfout)
{
    constexpr int DO2 = DOUT / 2;
    constexpr int DO4 = DOUT / 4;
    __shared__ ulonglong2 Ws4[3 * DIN * DO4];
    __shared__ u64 bs2[DO2];
    const u64* Wg = (const u64*)Wpair;
    const u64* Rg = (const u64*)root;
    u64* Wsu = (u64*)Ws4;
    for (int i = threadIdx.x; i < 2 * DIN * DO2; i += blockDim.x) Wsu[i] = Wg[i];
    for (int i = threadIdx.x; i < DIN * DO2; i += blockDim.x) Wsu[2 * DIN * DO2 + i] = Rg[i];
    if (threadIdx.x < DO2) bs2[threadIdx.x] = ((const u64*)bias)[threadIdx.x];
    __syncthreads();
    int row = blockIdx.x * blockDim.x + threadIdx.x;
    if (row >= NNODES) return;
    float xr[DIN];
    const float4* xp = (const float4*)(xin + (size_t)row * DIN);
#pragma unroll
    for (int k4 = 0; k4 < DIN / 4; k4++) {
        float4 v = xp[k4];
        xr[4*k4] = v.x; xr[4*k4+1] = v.y; xr[4*k4+2] = v.z; xr[4*k4+3] = v.w;
    }
    u64 a0[DO2], a1[DO2], a2[DO2];
#pragma unroll
    for (int p = 0; p < DO2; p++) { a0[p] = 0ull; a1[p] = 0ull; a2[p] = bs2[p]; }
#pragma unroll
    for (int k = 0; k < DIN; k++) {
        u64 xx = pack2(xr[k], xr[k]);
#pragma unroll
        for (int o = 0; o < DO4; o++) {
            ulonglong2 w0 = Ws4[k * DO4 + o];
            a0[2*o]   = ffma2(xx, w0.x, a0[2*o]);
            a0[2*o+1] = ffma2(xx, w0.y, a0[2*o+1]);
            ulonglong2 w1 = Ws4[(DIN + k) * DO4 + o];
            a1[2*o]   = ffma2(xx, w1.x, a1[2*o]);
            a1[2*o+1] = ffma2(xx, w1.y, a1[2*o+1]);
            ulonglong2 w2 = Ws4[(2 * DIN + k) * DO4 + o];
            a2[2*o]   = ffma2(xx, w2.x, a2[2*o]);
            a2[2*o+1] = ffma2(xx, w2.y, a2[2*o+1]);
        }
    }
    float4* y0 = (float4*)(Ycat + (size_t)row * DOUT);
    float4* y1 = (float4*)(Ycat + (size_t)(NNODES + row) * DOUT);
    float4* sf = (float4*)(selfout + (size_t)row * DOUT);
#pragma unroll
    for (int o = 0; o < DO4; o++) {
        float2 l0 = unpack2(a0[2*o]), h0 = unpack2(a0[2*o+1]);
        y0[o] = make_float4(l0.x, l0.y, h0.x, h0.y);
        float2 l1 = unpack2(a1[2*o]), h1 = unpack2(a1[2*o+1]);
        y1[o] = make_float4(l1.x, l1.y, h1.x, h1.y);
        float2 l2 = unpack2(a2[2*o]), h2 = unpack2(a2[2*o+1]);
        sf[o] = make_float4(l2.x, l2.y, h2.x, h2.y);
    }
}

// ---- CSR gather aggregation + fused finalize (unroll-4 for MLP) ----
template<int DOUT, bool RELU>
__global__ void __launch_bounds__(256) agg_csr_k(const int* __restrict__ rowptr,
                                                 const int* __restrict__ cnt,
                                                 const int* __restrict__ eidx,
                                                 const float* __restrict__ Y,
                                                 float* __restrict__ x)
{
    constexpr int DO4 = DOUT / 4;
    int gid = blockIdx.x * blockDim.x + threadIdx.x;
    int n = gid / DO4;
    int j = gid % DO4;
    if (n >= NNODES) return;
    int start = rowptr[n];
    int deg = cnt[n];
    const float4* Y4 = (const float4*)Y;
    float4 acc = make_float4(0.f, 0.f, 0.f, 0.f);
    int k = 0;
    for (; k + 4 <= deg; k += 4) {
        int r0 = eidx[start + k];
        int r1 = eidx[start + k + 1];
        int r2 = eidx[start + k + 2];
        int r3 = eidx[start + k + 3];
        float4 v0 = Y4[(size_t)r0 * DO4 + j];
        float4 v1 = Y4[(size_t)r1 * DO4 + j];
        float4 v2 = Y4[(size_t)r2 * DO4 + j];
        float4 v3 = Y4[(size_t)r3 * DO4 + j];
        acc.x += (v0.x + v1.x) + (v2.x + v3.x);
        acc.y += (v0.y + v1.y) + (v2.y + v3.y);
        acc.z += (v0.z + v1.z) + (v2.z + v3.z);
        acc.w += (v0.w + v1.w) + (v2.w + v3.w);
    }
    for (; k < deg; k++) {
        int r = eidx[start + k];
        float4 v = Y4[(size_t)r * DO4 + j];
        acc.x += v.x; acc.y += v.y; acc.z += v.z; acc.w += v.w;
    }
    float s = 1.0f / fmaxf((float)deg, 1.0f);
    float4* xp = (float4*)x + (size_t)n * DO4 + j;
    float4 v = *xp;
    v.x += acc.x * s; v.y += acc.y * s; v.z += acc.z * s; v.w += acc.w * s;
    if (RELU) {
        v.x = fmaxf(v.x, 0.f); v.y = fmaxf(v.y, 0.f);
        v.z = fmaxf(v.z, 0.f); v.w = fmaxf(v.w, 0.f);
    }
    *xp = v;
}

// ---- decode ----
__global__ void __launch_bounds__(256) decode_k(const int* __restrict__ ei,
                                                const int* __restrict__ et,
                                                const float* __restrict__ z,
                                                const float* __restrict__ w0, const float* __restrict__ b0,
                                                const float* __restrict__ w1, const float* __restrict__ b1,
                                                float* __restrict__ out, int E)
{
    __shared__ float4 Ws[128];   // [2][16][4]
    __shared__ float bs[32];
    for (int i = threadIdx.x; i < 128; i += blockDim.x)
        Ws[i] = (i < 64) ? ((const float4*)w0)[i] : ((const float4*)w1)[i - 64];
    if (threadIdx.x < 32)
        bs[threadIdx.x] = (threadIdx.x < 16) ? b0[threadIdx.x] : b1[threadIdx.x - 16];
    __syncthreads();
    int e = blockIdx.x * blockDim.x + threadIdx.x;
    if (e >= E) return;
    int s = ei[e];
    int d = ei[E + e];
    int t = et[e];
    const float4* zs4 = (const float4*)(z + (size_t)s * 16);
    const float4* zd4 = (const float4*)(z + (size_t)d * 16);
    float zs[16];
#pragma unroll
    for (int k4 = 0; k4 < 4; k4++) {
        float4 v = zs4[k4];
        zs[4*k4] = v.x; zs[4*k4+1] = v.y; zs[4*k4+2] = v.z; zs[4*k4+3] = v.w;
    }
    float4 zd[4];
#pragma unroll
    for (int k4 = 0; k4 < 4; k4++) zd[k4] = zd4[k4];
    int tb = t * 16;
    float4 acc[4];
#pragma unroll
    for (int o = 0; o < 4; o++) acc[o] = make_float4(bs[tb+4*o], bs[tb+4*o+1], bs[tb+4*o+2], bs[tb+4*o+3]);
#pragma unroll
    for (int k = 0; k < 16; k++) {
        float xv = zs[k];
#pragma unroll
        for (int o = 0; o < 4; o++) {
            float4 w = Ws[t * 64 + k * 4 + o];
            acc[o].x += xv * w.x; acc[o].y += xv * w.y;
            acc[o].z += xv * w.z; acc[o].w += xv * w.w;
        }
    }
    float sc = 0.f;
#pragma unroll
    for (int o = 0; o < 4; o++)
        sc += acc[o].x*zd[o].x + acc[o].y*zd[o].y + acc[o].z*zd[o].z + acc[o].w*zd[o].w;
    out[e] = sc;
}

extern "C" void kernel_launch(void* const* d_in, const int* in_sizes, int n_in,
                              void* d_out, int out_size)
{
    const float* x_paper = (const float*)d_in[0];
    const float* x_mesh  = (const float*)d_in[1];
    const float* tp_w = (const float*)d_in[2];
    const float* tp_b = (const float*)d_in[3];
    const float* tm_w = (const float*)d_in[4];
    const float* tm_b = (const float*)d_in[5];
    const float* comp1 = (const float*)d_in[6];
    const float* basis1 = (const float*)d_in[7];
    const float* root1 = (const float*)d_in[8];
    const float* bias1 = (const float*)d_in[9];
    const float* comp2 = (const float*)d_in[10];
    const float* basis2 = (const float*)d_in[11];
    const float* root2 = (const float*)d_in[12];
    const float* bias2 = (const float*)d_in[13];
    const float* comp3 = (const float*)d_in[14];
    const float* basis3 = (const float*)d_in[15];
    const float* root3 = (const float*)d_in[16];
    const float* bias3 = (const float*)d_in[17];
    const float* dpp_w = (const float*)d_in[18];
    const float* dpp_b = (const float*)d_in[19];
    const float* dpm_w = (const float*)d_in[20];
    const float* dpm_b = (const float*)d_in[21];
    const int* tei = (const int*)d_in[22];   // JAX x32: int32 arrays
    const int* tet = (const int*)d_in[23];
    const int* pei = (const int*)d_in[24];
    const int* pet = (const int*)d_in[25];
    const int* nei = (const int*)d_in[26];
    const int* net = (const int*)d_in[27];
    float* out = (float*)d_out;

    float *x0, *x1, *Y, *W;
    int *ssel, *dstv, *eidx, *cnt, *rowptr, *cursor, *pre, *bsum;
    cudaGetSymbolAddress((void**)&x0, g_x0);
    cudaGetSymbolAddress((void**)&x1, g_x1);
    cudaGetSymbolAddress((void**)&Y, g_Y);
    cudaGetSymbolAddress((void**)&W, g_W);
    cudaGetSymbolAddress((void**)&ssel, g_ssel);
    cudaGetSymbolAddress((void**)&dstv, g_dst);
    cudaGetSymbolAddress((void**)&eidx, g_eidx);
    cudaGetSymbolAddress((void**)&cnt, g_cnt);
    cudaGetSymbolAddress((void**)&rowptr, g_rowptr);
    cudaGetSymbolAddress((void**)&cursor, g_cursor);
    cudaGetSymbolAddress((void**)&pre, g_pre);
    cudaGetSymbolAddress((void**)&bsum, g_bsum);

    const int EB = (E_TR + 255) / 256;
    const int NB = (NNODES + 255) / 256;

    // ncu captures the 5th graph node -> keep encode_k<512> there.
    cudaMemsetAsync(cnt, 0, NNODES * sizeof(int));                       // 1
    hist_k<<<EB, 256>>>(tei, tet, ssel, dstv, cnt);                      // 2
    scan1_k<<<NBLK_SCAN, 256>>>(cnt, pre, bsum);                         // 3
    scan2_k<<<1, 256>>>(bsum, NBLK_SCAN);                                // 4
    encode_k<512><<<(N_PAPER + 255) / 256, 256>>>(x_paper, tp_w, tp_b, x0, N_PAPER);  // 5 <- profiled
    encode_k<128><<<(N_MESH + 255) / 256, 256>>>(x_mesh, tm_w, tm_b,
                                                 x0 + (size_t)N_PAPER * 16, N_MESH);  // 6
    scan3_k<<<NB, 256>>>(pre, bsum, rowptr, cursor);                     // 7
    scatter_k<<<EB, 256>>>(ssel, dstv, cursor, eidx);                    // 8

    // ---- layer 1: 16 -> 32, relu ----
    make_W_k<<<8, 256>>>(comp1, basis1, W, 16 * 32);
    transform3_k<16, 32><<<NB, 256>>>(x0, W, root1, bias1, Y, x1);
    agg_csr_k<32, true><<<(NNODES * 8 + 255) / 256, 256>>>(rowptr, cnt, eidx, Y, x1);

    // ---- layer 2: 32 -> 32, relu ----
    make_W_k<<<8, 256>>>(comp2, basis2, W, 32 * 32);
    transform3_k<32, 32><<<NB, 256>>>(x1, W, root2, bias2, Y, x0);
    agg_csr_k<32, true><<<(NNODES * 8 + 255) / 256, 256>>>(rowptr, cnt, eidx, Y, x0);

    // ---- layer 3: 32 -> 16, no relu -> z in x1 ----
    make_W_k<<<8, 256>>>(comp3, basis3, W, 32 * 16);
    transform3_k<32, 16><<<NB, 256>>>(x0, W, root3, bias3, Y, x1);
    agg_csr_k<16, false><<<(NNODES * 4 + 255) / 256, 256>>>(rowptr, cnt, eidx, Y, x1);

    // ---- decode: pos then neg ----
    decode_k<<<(E_P + 255) / 256, 256>>>(pei, pet, x1, dpp_w, dpp_b, dpm_w, dpm_b, out, E_P);
    decode_k<<<(E_N + 255) / 256, 256>>>(nei, net, x1, dpp_w, dpp_b, dpm_w, dpm_b, out + E_P, E_N);
}